// round 2
// baseline (speedup 1.0000x reference)
#include <cuda_runtime.h>
#include <math.h>

#define DIMC   512
#define NHEADS 8
#define DHD    64
#define NDEPTH 2
#define BBATCH 2
#define NSEQ   1024
#define DINNER 512
#define FFD    2048
#define MTOK   (BBATCH*NSEQ)   // 2048 tokens
#define EPSV   1e-6f
#define SCALEV 0.125f          // DH^-0.5

// ---------------- scratch (static device globals; no allocations) ----------
__device__ float2 g_x [MTOK*DIMC];         // residual stream (complex)
__device__ float2 g_h [MTOK*DIMC];         // normed hidden
__device__ float2 g_q [MTOK*DINNER];       // q projection
__device__ float2 g_kv[MTOK*2*DINNER];     // kv projection
__device__ float  g_o4[4*BBATCH*NHEADS*NSEQ*DHD]; // 4 real attention outputs
__device__ float2 g_oc[MTOK*DINNER];       // combined complex attention out
__device__ float2 g_h1[MTOK*FFD];          // FF intermediate
__device__ float  g_cos[NSEQ*DHD];
__device__ float  g_sin[NSEQ*DHD];

// ---------------- small kernels --------------------------------------------
__global__ void copy_in(const float2* __restrict__ x) {
    int i = blockIdx.x * 256 + threadIdx.x;
    g_x[i] = x[i];
}

__global__ void rope_table() {
    int i = blockIdx.x * 256 + threadIdx.x;
    if (i < NSEQ * DHD) {
        int n = i / DHD, d = i % DHD;
        float invf = powf(10000.0f, -((float)d) / (float)DHD);
        float f = (float)n * invf;
        g_cos[i] = cosf(f);
        g_sin[i] = sinf(f);
    }
}

// rmsnorm over DIM complex elems per token, times complex gamma
__global__ void rmsnorm_k(const float2* __restrict__ in,
                          const float2* __restrict__ gamma,
                          float2* __restrict__ out) {
    int t = blockIdx.x;
    const float2* xp = in + (size_t)t * DIMC;
    __shared__ float red[256];
    float s = 0.f;
    for (int i = threadIdx.x; i < DIMC; i += 256) {
        float2 v = xp[i];
        s += v.x * v.x + v.y * v.y;
    }
    red[threadIdx.x] = s;
    __syncthreads();
    for (int o = 128; o > 0; o >>= 1) {
        if (threadIdx.x < o) red[threadIdx.x] += red[threadIdx.x + o];
        __syncthreads();
    }
    float inv = rsqrtf(red[0] / (float)DIMC + EPSV);
    for (int i = threadIdx.x; i < DIMC; i += 256) {
        float2 v = xp[i];
        float2 g = gamma[i];
        float xr = v.x * inv, xi = v.y * inv;
        out[(size_t)t * DIMC + i] = make_float2(xr * g.x - xi * g.y,
                                                xr * g.y + xi * g.x);
    }
}

// ---------------- complex GEMM: C[M x Ncols] = A[M x K] @ W[K x Ncols] -----
// optional bias[Ncols], optional residual res (same shape as C)
__global__ __launch_bounds__(256)
void cgemm(const float2* __restrict__ A, const float2* __restrict__ W,
           const float2* __restrict__ bias, const float2* __restrict__ res,
           float2* __restrict__ C, int K, int Ncols) {
    __shared__ float2 As[16][64];
    __shared__ float2 Ws[16][64];
    int tx = threadIdx.x & 15, ty = threadIdx.x >> 4;
    int m0 = blockIdx.y * 64, n0 = blockIdx.x * 64;

    float2 acc[4][4];
#pragma unroll
    for (int i = 0; i < 4; i++)
#pragma unroll
        for (int j = 0; j < 4; j++) acc[i][j] = make_float2(0.f, 0.f);

    for (int k0 = 0; k0 < K; k0 += 16) {
#pragma unroll
        for (int t = 0; t < 4; t++) {
            int idx = threadIdx.x + t * 256;
            int kk = idx & 15, m = idx >> 4;      // coalesced over kk
            As[kk][m] = A[(size_t)(m0 + m) * K + k0 + kk];
        }
#pragma unroll
        for (int t = 0; t < 4; t++) {
            int idx = threadIdx.x + t * 256;
            int n = idx & 63, kk = idx >> 6;      // coalesced over n
            Ws[kk][n] = W[(size_t)(k0 + kk) * Ncols + n0 + n];
        }
        __syncthreads();
#pragma unroll
        for (int kk = 0; kk < 16; kk++) {
            float2 a[4], w[4];
#pragma unroll
            for (int i = 0; i < 4; i++) a[i] = As[kk][ty + 16 * i];
#pragma unroll
            for (int j = 0; j < 4; j++) w[j] = Ws[kk][tx + 16 * j];
#pragma unroll
            for (int i = 0; i < 4; i++)
#pragma unroll
                for (int j = 0; j < 4; j++) {
                    acc[i][j].x = fmaf(a[i].x, w[j].x, acc[i][j].x);
                    acc[i][j].x = fmaf(-a[i].y, w[j].y, acc[i][j].x);
                    acc[i][j].y = fmaf(a[i].x, w[j].y, acc[i][j].y);
                    acc[i][j].y = fmaf(a[i].y, w[j].x, acc[i][j].y);
                }
        }
        __syncthreads();
    }
#pragma unroll
    for (int i = 0; i < 4; i++)
#pragma unroll
        for (int j = 0; j < 4; j++) {
            int row = m0 + ty + 16 * i;
            int col = n0 + tx + 16 * j;
            float2 v = acc[i][j];
            if (bias) { float2 bb = bias[col]; v.x += bb.x; v.y += bb.y; }
            if (res)  { float2 rr = res[(size_t)row * Ncols + col]; v.x += rr.x; v.y += rr.y; }
            C[(size_t)row * Ncols + col] = v;
        }
}

// ---------------- RoPE (complex multiply by e^{i n w_d}) in place ----------
__global__ void rope_apply(float2* __restrict__ buf, int rowStride) {
    int i = blockIdx.x * 256 + threadIdx.x;   // [0, B*N*INNER)
    int e = i % DINNER;
    int n = (i / DINNER) % NSEQ;
    int b = i / (DINNER * NSEQ);
    int d = e % DHD;
    float c = g_cos[n * DHD + d], s = g_sin[n * DHD + d];
    float2* p = buf + (size_t)(b * NSEQ + n) * rowStride + e;
    float2 v = *p;
    *p = make_float2(v.x * c - v.y * s, v.x * s + v.y * c);
}

// ---------------- flash attention, one warp per query row ------------------
// grid: (NSEQ/8, NHEADS, BBATCH*4), block 256 (8 warps)
// replica r: q uses (r>=2 ? imag : real), k uses (r&1 ? -imag : real),
//            v uses (r>=2 ? imag : real)
__global__ __launch_bounds__(256)
void flash_attn() {
    int warp = threadIdx.x >> 5, lane = threadIdx.x & 31;
    int b = blockIdx.z >> 2, r = blockIdx.z & 3;
    int h = blockIdx.y;
    int row = blockIdx.x * 8 + warp;
    bool qimag = (r >= 2);
    bool kneg  = (r & 1);

    __shared__ float qs[8][DHD];
    __shared__ float ks[32][DHD + 1];
    __shared__ float vs[32][DHD + 1];

    for (int i = threadIdx.x; i < 8 * DHD; i += 256) {
        int rr = i >> 6, d = i & 63;
        float2 v = g_q[(size_t)(b * NSEQ + blockIdx.x * 8 + rr) * DINNER + h * DHD + d];
        qs[rr][d] = qimag ? v.y : v.x;
    }

    float m = -INFINITY, l = 0.f, o0 = 0.f, o1 = 0.f;

    for (int c0 = 0; c0 < NSEQ; c0 += 32) {
        __syncthreads();
        for (int i = threadIdx.x; i < 32 * DHD; i += 256) {
            int kk = i >> 6, d = i & 63;
            const float2* kvrow = g_kv + (size_t)(b * NSEQ + c0 + kk) * (2 * DINNER) + h * DHD + d;
            float2 kc = kvrow[0];
            float2 vc = kvrow[DINNER];
            ks[kk][d] = kneg ? -kc.y : kc.x;
            vs[kk][d] = qimag ? vc.y : vc.x;
        }
        __syncthreads();

        float s = 0.f;
#pragma unroll
        for (int d = 0; d < DHD; d++) s = fmaf(qs[warp][d], ks[lane][d], s);
        s *= SCALEV;

        float mc = s;
#pragma unroll
        for (int o = 16; o; o >>= 1) mc = fmaxf(mc, __shfl_xor_sync(0xffffffffu, mc, o));
        float mnew = fmaxf(m, mc);
        float corr = expf(m - mnew);
        l *= corr; o0 *= corr; o1 *= corr;

        float p = expf(s - mnew);
        float ps = p;
#pragma unroll
        for (int o = 16; o; o >>= 1) ps += __shfl_xor_sync(0xffffffffu, ps, o);
        l += ps;

#pragma unroll
        for (int jj = 0; jj < 32; jj++) {
            float pj = __shfl_sync(0xffffffffu, p, jj);
            o0 = fmaf(pj, vs[jj][lane], o0);
            o1 = fmaf(pj, vs[jj][lane + 32], o1);
        }
        m = mnew;
    }

    float invl = 1.f / l;
    size_t base = ((size_t)((r * BBATCH + b) * NHEADS + h) * NSEQ + row) * DHD;
    g_o4[base + lane]      = o0 * invl;
    g_o4[base + lane + 32] = o1 * invl;
}

// combine 4 real attention planes -> complex, heads back to flat layout
__global__ void combine_o() {
    int i = blockIdx.x * 256 + threadIdx.x;  // [0, B*N*INNER)
    int d  = i % DHD;
    int hh = (i / DHD) % NHEADS;
    int n  = (i / DINNER) % NSEQ;
    int b  = i / (DINNER * NSEQ);
    size_t idx4 = ((size_t)(b * NHEADS + hh) * NSEQ + n) * DHD + d;
    const size_t plane = (size_t)BBATCH * NHEADS * NSEQ * DHD;
    float rr = g_o4[idx4];
    float ri = g_o4[plane + idx4];
    float ir = g_o4[2 * plane + idx4];
    float ii = g_o4[3 * plane + idx4];
    g_oc[i] = make_float2(rr - ii, ri + ir);
}

// h <- relu(|h| + mod_bias)^2 * h/|h|
__global__ void nonlin_k(const float* __restrict__ mod_bias, int layer) {
    int i = blockIdx.x * 256 + threadIdx.x;   // [0, MTOK*FFD)
    float2 v = g_h1[i];
    float mag = sqrtf(v.x * v.x + v.y * v.y);
    float t = mag + mod_bias[layer];
    float c = t > 0.f ? t * t : 0.f;
    float2 out;
    if (mag > 0.f) {
        float sc = c / mag;
        out = make_float2(v.x * sc, v.y * sc);
    } else {
        out = make_float2(c, 0.f);
    }
    g_h1[i] = out;
}

// ---------------- host orchestration ---------------------------------------
extern "C" void kernel_launch(void* const* d_in, const int* in_sizes, int n_in,
                              void* d_out, int out_size) {
    const float2* x           = (const float2*)d_in[0];
    const float2* gamma_attn  = (const float2*)d_in[1];
    const float2* Wq          = (const float2*)d_in[2];
    const float2* Wkv         = (const float2*)d_in[3];
    const float2* Wo          = (const float2*)d_in[4];
    const float2* gamma_ff    = (const float2*)d_in[5];
    const float2* W1          = (const float2*)d_in[6];
    const float2* b1          = (const float2*)d_in[7];
    const float*  mod_bias    = (const float*)d_in[8];
    const float2* W2          = (const float2*)d_in[9];
    const float2* b2          = (const float2*)d_in[10];
    const float2* gamma_final = (const float2*)d_in[11];

    float2 *px, *ph, *pq, *pkv, *poc, *ph1;
    cudaGetSymbolAddress((void**)&px,  g_x);
    cudaGetSymbolAddress((void**)&ph,  g_h);
    cudaGetSymbolAddress((void**)&pq,  g_q);
    cudaGetSymbolAddress((void**)&pkv, g_kv);
    cudaGetSymbolAddress((void**)&poc, g_oc);
    cudaGetSymbolAddress((void**)&ph1, g_h1);

    copy_in<<<MTOK * DIMC / 256, 256>>>(x);
    rope_table<<<(NSEQ * DHD + 255) / 256, 256>>>();

    for (int l = 0; l < NDEPTH; l++) {
        // attention block
        rmsnorm_k<<<MTOK, 256>>>(px, gamma_attn + (size_t)l * DIMC, ph);
        cgemm<<<dim3(DINNER / 64, MTOK / 64), 256>>>(
            ph, Wq + (size_t)l * DIMC * DINNER, nullptr, nullptr, pq, DIMC, DINNER);
        cgemm<<<dim3(2 * DINNER / 64, MTOK / 64), 256>>>(
            ph, Wkv + (size_t)l * DIMC * 2 * DINNER, nullptr, nullptr, pkv, DIMC, 2 * DINNER);
        rope_apply<<<BBATCH * NSEQ * DINNER / 256, 256>>>(pq, DINNER);
        rope_apply<<<BBATCH * NSEQ * DINNER / 256, 256>>>(pkv, 2 * DINNER);
        flash_attn<<<dim3(NSEQ / 8, NHEADS, BBATCH * 4), 256>>>();
        combine_o<<<BBATCH * NSEQ * DINNER / 256, 256>>>();
        cgemm<<<dim3(DIMC / 64, MTOK / 64), 256>>>(
            poc, Wo + (size_t)l * DINNER * DIMC, nullptr, px, px, DINNER, DIMC);

        // feed-forward block
        rmsnorm_k<<<MTOK, 256>>>(px, gamma_ff + (size_t)l * DIMC, ph);
        cgemm<<<dim3(FFD / 64, MTOK / 64), 256>>>(
            ph, W1 + (size_t)l * DIMC * FFD, b1 + (size_t)l * FFD, nullptr, ph1, DIMC, FFD);
        nonlin_k<<<MTOK * FFD / 256, 256>>>(mod_bias, l);
        cgemm<<<dim3(DIMC / 64, MTOK / 64), 256>>>(
            ph1, W2 + (size_t)l * FFD * DIMC, b2 + (size_t)l * DIMC, px, px, FFD, DIMC);
    }

    rmsnorm_k<<<MTOK, 256>>>(px, gamma_final, (float2*)d_out);
}

// round 3
// speedup vs baseline: 1.4606x; 1.4606x over previous
#include <cuda_runtime.h>
#include <math.h>
#include <stdint.h>

#define DIMC   512
#define NHEADS 8
#define DHD    64
#define NDEPTH 2
#define BBATCH 2
#define NSEQ   1024
#define DINNER 512
#define FFD    2048
#define MTOK   (BBATCH*NSEQ)   // 2048 tokens
#define EPSV   1e-6f
#define SCALEV 0.125f          // DH^-0.5

// ---------------- scratch (static device globals; no allocations) ----------
__device__ float2 g_x [MTOK*DIMC];
__device__ float2 g_h [MTOK*DIMC];
__device__ float2 g_q [MTOK*DINNER];
__device__ float2 g_kv[MTOK*2*DINNER];
__device__ float  g_o4[4*BBATCH*NHEADS*NSEQ*DHD];
__device__ float2 g_oc[MTOK*DINNER];
__device__ float2 g_h1[MTOK*FFD];
__device__ float  g_cos[NSEQ*DHD];
__device__ float  g_sin[NSEQ*DHD];

// ---------------- small kernels --------------------------------------------
__global__ void copy_in(const float2* __restrict__ x) {
    int i = blockIdx.x * 256 + threadIdx.x;
    g_x[i] = x[i];
}

__global__ void rope_table() {
    int i = blockIdx.x * 256 + threadIdx.x;
    if (i < NSEQ * DHD) {
        int n = i / DHD, d = i % DHD;
        float invf = powf(10000.0f, -((float)d) / (float)DHD);
        float f = (float)n * invf;
        g_cos[i] = cosf(f);
        g_sin[i] = sinf(f);
    }
}

__global__ void rmsnorm_k(const float2* __restrict__ in,
                          const float2* __restrict__ gamma,
                          float2* __restrict__ out) {
    int t = blockIdx.x;
    const float2* xp = in + (size_t)t * DIMC;
    __shared__ float red[256];
    float s = 0.f;
    for (int i = threadIdx.x; i < DIMC; i += 256) {
        float2 v = xp[i];
        s += v.x * v.x + v.y * v.y;
    }
    red[threadIdx.x] = s;
    __syncthreads();
    for (int o = 128; o > 0; o >>= 1) {
        if (threadIdx.x < o) red[threadIdx.x] += red[threadIdx.x + o];
        __syncthreads();
    }
    float inv = rsqrtf(red[0] / (float)DIMC + EPSV);
    for (int i = threadIdx.x; i < DIMC; i += 256) {
        float2 v = xp[i];
        float2 g = gamma[i];
        float xr = v.x * inv, xi = v.y * inv;
        out[(size_t)t * DIMC + i] = make_float2(xr * g.x - xi * g.y,
                                                xr * g.y + xi * g.x);
    }
}

// ---------------- tf32 tensor-core complex GEMM -----------------------------
// C[M x N] = A[M x K] @ W[K x N]   (complex, float2 interleaved)
// block tile 128x64, BK=16, 8 warps each 32x32.
#define BM 128
#define BN 64
#define BK 16
#define ASTR 20   // A smem stride (floats): conflict-free fragment reads
#define BSTR 17   // B smem stride: conflict-free transposed stores

__device__ __forceinline__ uint32_t f2tf(float x) {
    uint32_t r;
    asm("cvt.rna.tf32.f32 %0, %1;" : "=r"(r) : "f"(x));
    return r;
}

__device__ __forceinline__ void mma8(float* c, const uint32_t* a, const uint32_t* b) {
    asm volatile(
        "mma.sync.aligned.m16n8k8.row.col.f32.tf32.tf32.f32 "
        "{%0,%1,%2,%3}, {%4,%5,%6,%7}, {%8,%9}, {%0,%1,%2,%3};"
        : "+f"(c[0]), "+f"(c[1]), "+f"(c[2]), "+f"(c[3])
        : "r"(a[0]), "r"(a[1]), "r"(a[2]), "r"(a[3]), "r"(b[0]), "r"(b[1]));
}

__global__ __launch_bounds__(256)
void cgemm_tc(const float2* __restrict__ A, const float2* __restrict__ W,
              const float2* __restrict__ bias, const float2* __restrict__ res,
              float2* __restrict__ C, int K, int N) {
    __shared__ float Asr[BM][ASTR];
    __shared__ float Asi[BM][ASTR];
    __shared__ float Bsr[BN][BSTR];
    __shared__ float Bsi[BN][BSTR];

    const int tid  = threadIdx.x;
    const int lane = tid & 31;
    const int warp = tid >> 5;
    const int mwarp = warp >> 1;          // 0..3
    const int nwarp = warp & 1;           // 0..1
    const int mbase = mwarp * 32;
    const int nbase = nwarp * 32;
    const int gr = lane >> 2;             // 0..7
    const int cc = lane & 3;              // 0..3
    const int m0 = blockIdx.y * BM;
    const int n0 = blockIdx.x * BN;

    float accr[2][4][4], acci[2][4][4];
#pragma unroll
    for (int mt = 0; mt < 2; mt++)
#pragma unroll
        for (int nt = 0; nt < 4; nt++)
#pragma unroll
            for (int e = 0; e < 4; e++) { accr[mt][nt][e] = 0.f; acci[mt][nt][e] = 0.f; }

    const int nkb = K / BK;
    float2 aReg[8], bReg[4];

    // prologue: fetch block 0
#pragma unroll
    for (int t = 0; t < 8; t++) {
        int idx = tid + t * 256;
        int m = idx >> 4, kk = idx & 15;
        aReg[t] = A[(size_t)(m0 + m) * K + kk];
    }
#pragma unroll
    for (int t = 0; t < 4; t++) {
        int idx = tid + t * 256;
        int n = idx & 63, kk = idx >> 6;
        bReg[t] = W[(size_t)kk * N + n0 + n];
    }
#pragma unroll
    for (int t = 0; t < 8; t++) {
        int idx = tid + t * 256;
        int m = idx >> 4, kk = idx & 15;
        Asr[m][kk] = aReg[t].x; Asi[m][kk] = aReg[t].y;
    }
#pragma unroll
    for (int t = 0; t < 4; t++) {
        int idx = tid + t * 256;
        int n = idx & 63, kk = idx >> 6;
        Bsr[n][kk] = bReg[t].x; Bsi[n][kk] = bReg[t].y;
    }
    __syncthreads();

    for (int kb = 0; kb < nkb; kb++) {
        // prefetch next block into registers (latency overlapped with mma)
        if (kb + 1 < nkb) {
            int k0 = (kb + 1) * BK;
#pragma unroll
            for (int t = 0; t < 8; t++) {
                int idx = tid + t * 256;
                int m = idx >> 4, kk = idx & 15;
                aReg[t] = A[(size_t)(m0 + m) * K + k0 + kk];
            }
#pragma unroll
            for (int t = 0; t < 4; t++) {
                int idx = tid + t * 256;
                int n = idx & 63, kk = idx >> 6;
                bReg[t] = W[(size_t)(k0 + kk) * N + n0 + n];
            }
        }

        // compute on current smem block
#pragma unroll
        for (int ks = 0; ks < BK; ks += 8) {
            uint32_t ar[2][4], ai[2][4], nai[2][4];
#pragma unroll
            for (int mt = 0; mt < 2; mt++) {
                int r = mbase + mt * 16 + gr;
                ar[mt][0] = f2tf(Asr[r][ks + cc]);
                ar[mt][1] = f2tf(Asr[r + 8][ks + cc]);
                ar[mt][2] = f2tf(Asr[r][ks + cc + 4]);
                ar[mt][3] = f2tf(Asr[r + 8][ks + cc + 4]);
                ai[mt][0] = f2tf(Asi[r][ks + cc]);
                ai[mt][1] = f2tf(Asi[r + 8][ks + cc]);
                ai[mt][2] = f2tf(Asi[r][ks + cc + 4]);
                ai[mt][3] = f2tf(Asi[r + 8][ks + cc + 4]);
#pragma unroll
                for (int e = 0; e < 4; e++) nai[mt][e] = ai[mt][e] ^ 0x80000000u;
            }
            uint32_t br[4][2], bi[4][2];
#pragma unroll
            for (int nt = 0; nt < 4; nt++) {
                int n = nbase + nt * 8 + gr;
                br[nt][0] = f2tf(Bsr[n][ks + cc]);
                br[nt][1] = f2tf(Bsr[n][ks + cc + 4]);
                bi[nt][0] = f2tf(Bsi[n][ks + cc]);
                bi[nt][1] = f2tf(Bsi[n][ks + cc + 4]);
            }
#pragma unroll
            for (int mt = 0; mt < 2; mt++)
#pragma unroll
                for (int nt = 0; nt < 4; nt++) {
                    mma8(accr[mt][nt], ar[mt],  br[nt]);
                    mma8(accr[mt][nt], nai[mt], bi[nt]);
                    mma8(acci[mt][nt], ar[mt],  bi[nt]);
                    mma8(acci[mt][nt], ai[mt],  br[nt]);
                }
        }
        __syncthreads();

        if (kb + 1 < nkb) {
#pragma unroll
            for (int t = 0; t < 8; t++) {
                int idx = tid + t * 256;
                int m = idx >> 4, kk = idx & 15;
                Asr[m][kk] = aReg[t].x; Asi[m][kk] = aReg[t].y;
            }
#pragma unroll
            for (int t = 0; t < 4; t++) {
                int idx = tid + t * 256;
                int n = idx & 63, kk = idx >> 6;
                Bsr[n][kk] = bReg[t].x; Bsi[n][kk] = bReg[t].y;
            }
            __syncthreads();
        }
    }

    // epilogue: c0,c1 are adjacent columns -> one 32B (2x float2) store
#pragma unroll
    for (int mt = 0; mt < 2; mt++)
#pragma unroll
        for (int nt = 0; nt < 4; nt++) {
#pragma unroll
            for (int half = 0; half < 2; half++) {   // half=0: rows gr; half=1: rows gr+8
                int row = m0 + mbase + mt * 16 + gr + half * 8;
                int col = n0 + nbase + nt * 8 + cc * 2;
                float r0 = accr[mt][nt][half * 2 + 0];
                float i0 = acci[mt][nt][half * 2 + 0];
                float r1 = accr[mt][nt][half * 2 + 1];
                float i1 = acci[mt][nt][half * 2 + 1];
                if (bias) {
                    float2 b0 = bias[col], b1 = bias[col + 1];
                    r0 += b0.x; i0 += b0.y; r1 += b1.x; i1 += b1.y;
                }
                if (res) {
                    const float4 rr = *reinterpret_cast<const float4*>(res + (size_t)row * N + col);
                    r0 += rr.x; i0 += rr.y; r1 += rr.z; i1 += rr.w;
                }
                *reinterpret_cast<float4*>(C + (size_t)row * N + col) =
                    make_float4(r0, i0, r1, i1);
            }
        }
}

// ---------------- RoPE ------------------------------------------------------
__global__ void rope_apply(float2* __restrict__ buf, int rowStride) {
    int i = blockIdx.x * 256 + threadIdx.x;
    int e = i % DINNER;
    int n = (i / DINNER) % NSEQ;
    int b = i / (DINNER * NSEQ);
    int d = e % DHD;
    float c = g_cos[n * DHD + d], s = g_sin[n * DHD + d];
    float2* p = buf + (size_t)(b * NSEQ + n) * rowStride + e;
    float2 v = *p;
    *p = make_float2(v.x * c - v.y * s, v.x * s + v.y * c);
}

// ---------------- flash attention, one warp per query row ------------------
__global__ __launch_bounds__(256)
void flash_attn() {
    int warp = threadIdx.x >> 5, lane = threadIdx.x & 31;
    int b = blockIdx.z >> 2, r = blockIdx.z & 3;
    int h = blockIdx.y;
    int row = blockIdx.x * 8 + warp;
    bool qimag = (r >= 2);
    bool kneg  = (r & 1);

    __shared__ float qs[8][DHD];
    __shared__ float ks[32][DHD + 1];
    __shared__ float vs[32][DHD + 1];

    for (int i = threadIdx.x; i < 8 * DHD; i += 256) {
        int rr = i >> 6, d = i & 63;
        float2 v = g_q[(size_t)(b * NSEQ + blockIdx.x * 8 + rr) * DINNER + h * DHD + d];
        qs[rr][d] = qimag ? v.y : v.x;
    }

    float m = -INFINITY, l = 0.f, o0 = 0.f, o1 = 0.f;

    for (int c0 = 0; c0 < NSEQ; c0 += 32) {
        __syncthreads();
        for (int i = threadIdx.x; i < 32 * DHD; i += 256) {
            int kk = i >> 6, d = i & 63;
            const float2* kvrow = g_kv + (size_t)(b * NSEQ + c0 + kk) * (2 * DINNER) + h * DHD + d;
            float2 kc = kvrow[0];
            float2 vc = kvrow[DINNER];
            ks[kk][d] = kneg ? -kc.y : kc.x;
            vs[kk][d] = qimag ? vc.y : vc.x;
        }
        __syncthreads();

        float s = 0.f;
#pragma unroll
        for (int d = 0; d < DHD; d++) s = fmaf(qs[warp][d], ks[lane][d], s);
        s *= SCALEV;

        float mc = s;
#pragma unroll
        for (int o = 16; o; o >>= 1) mc = fmaxf(mc, __shfl_xor_sync(0xffffffffu, mc, o));
        float mnew = fmaxf(m, mc);
        float corr = expf(m - mnew);
        l *= corr; o0 *= corr; o1 *= corr;

        float p = expf(s - mnew);
        float ps = p;
#pragma unroll
        for (int o = 16; o; o >>= 1) ps += __shfl_xor_sync(0xffffffffu, ps, o);
        l += ps;

#pragma unroll
        for (int jj = 0; jj < 32; jj++) {
            float pj = __shfl_sync(0xffffffffu, p, jj);
            o0 = fmaf(pj, vs[jj][lane], o0);
            o1 = fmaf(pj, vs[jj][lane + 32], o1);
        }
        m = mnew;
    }

    float invl = 1.f / l;
    size_t base = ((size_t)((r * BBATCH + b) * NHEADS + h) * NSEQ + row) * DHD;
    g_o4[base + lane]      = o0 * invl;
    g_o4[base + lane + 32] = o1 * invl;
}

__global__ void combine_o() {
    int i = blockIdx.x * 256 + threadIdx.x;
    int d  = i % DHD;
    int hh = (i / DHD) % NHEADS;
    int n  = (i / DINNER) % NSEQ;
    int b  = i / (DINNER * NSEQ);
    size_t idx4 = ((size_t)(b * NHEADS + hh) * NSEQ + n) * DHD + d;
    const size_t plane = (size_t)BBATCH * NHEADS * NSEQ * DHD;
    float rr = g_o4[idx4];
    float ri = g_o4[plane + idx4];
    float ir = g_o4[2 * plane + idx4];
    float ii = g_o4[3 * plane + idx4];
    g_oc[i] = make_float2(rr - ii, ri + ir);
}

__global__ void nonlin_k(const float* __restrict__ mod_bias, int layer) {
    int i = blockIdx.x * 256 + threadIdx.x;
    float2 v = g_h1[i];
    float mag = sqrtf(v.x * v.x + v.y * v.y);
    float t = mag + mod_bias[layer];
    float c = t > 0.f ? t * t : 0.f;
    float2 out;
    if (mag > 0.f) {
        float sc = c / mag;
        out = make_float2(v.x * sc, v.y * sc);
    } else {
        out = make_float2(c, 0.f);
    }
    g_h1[i] = out;
}

// ---------------- host orchestration ---------------------------------------
extern "C" void kernel_launch(void* const* d_in, const int* in_sizes, int n_in,
                              void* d_out, int out_size) {
    const float2* x           = (const float2*)d_in[0];
    const float2* gamma_attn  = (const float2*)d_in[1];
    const float2* Wq          = (const float2*)d_in[2];
    const float2* Wkv         = (const float2*)d_in[3];
    const float2* Wo          = (const float2*)d_in[4];
    const float2* gamma_ff    = (const float2*)d_in[5];
    const float2* W1          = (const float2*)d_in[6];
    const float2* b1          = (const float2*)d_in[7];
    const float*  mod_bias    = (const float*)d_in[8];
    const float2* W2          = (const float2*)d_in[9];
    const float2* b2          = (const float2*)d_in[10];
    const float2* gamma_final = (const float2*)d_in[11];

    float2 *px, *ph, *pq, *pkv, *poc, *ph1;
    cudaGetSymbolAddress((void**)&px,  g_x);
    cudaGetSymbolAddress((void**)&ph,  g_h);
    cudaGetSymbolAddress((void**)&pq,  g_q);
    cudaGetSymbolAddress((void**)&pkv, g_kv);
    cudaGetSymbolAddress((void**)&poc, g_oc);
    cudaGetSymbolAddress((void**)&ph1, g_h1);

    copy_in<<<MTOK * DIMC / 256, 256>>>(x);
    rope_table<<<(NSEQ * DHD + 255) / 256, 256>>>();

    for (int l = 0; l < NDEPTH; l++) {
        rmsnorm_k<<<MTOK, 256>>>(px, gamma_attn + (size_t)l * DIMC, ph);
        cgemm_tc<<<dim3(DINNER / BN, MTOK / BM), 256>>>(
            ph, Wq + (size_t)l * DIMC * DINNER, nullptr, nullptr, pq, DIMC, DINNER);
        cgemm_tc<<<dim3(2 * DINNER / BN, MTOK / BM), 256>>>(
            ph, Wkv + (size_t)l * DIMC * 2 * DINNER, nullptr, nullptr, pkv, DIMC, 2 * DINNER);
        rope_apply<<<BBATCH * NSEQ * DINNER / 256, 256>>>(pq, DINNER);
        rope_apply<<<BBATCH * NSEQ * DINNER / 256, 256>>>(pkv, 2 * DINNER);
        flash_attn<<<dim3(NSEQ / 8, NHEADS, BBATCH * 4), 256>>>();
        combine_o<<<BBATCH * NSEQ * DINNER / 256, 256>>>();
        cgemm_tc<<<dim3(DIMC / BN, MTOK / BM), 256>>>(
            poc, Wo + (size_t)l * DINNER * DIMC, nullptr, px, px, DINNER, DIMC);

        rmsnorm_k<<<MTOK, 256>>>(px, gamma_ff + (size_t)l * DIMC, ph);
        cgemm_tc<<<dim3(FFD / BN, MTOK / BM), 256>>>(
            ph, W1 + (size_t)l * DIMC * FFD, b1 + (size_t)l * FFD, nullptr, ph1, DIMC, FFD);
        nonlin_k<<<MTOK * FFD / 256, 256>>>(mod_bias, l);
        cgemm_tc<<<dim3(DIMC / BN, MTOK / BM), 256>>>(
            ph1, W2 + (size_t)l * FFD * DIMC, b2 + (size_t)l * DIMC, px, px, FFD, DIMC);
    }

    rmsnorm_k<<<MTOK, 256>>>(px, gamma_final, (float2*)d_out);
}

// round 4
// speedup vs baseline: 4.3296x; 2.9642x over previous
#include <cuda_runtime.h>
#include <math.h>
#include <stdint.h>

#define DIMC   512
#define NHEADS 8
#define DHD    64
#define NDEPTH 2
#define BBATCH 2
#define NSEQ   1024
#define DINNER 512
#define FFD    2048
#define MTOK   (BBATCH*NSEQ)
#define EPSV   1e-6f
#define SCALEV 0.125f

// ---------------- scratch ---------------------------------------------------
__device__ float2 g_x [MTOK*DIMC];
__device__ float2 g_h [MTOK*DIMC];
__device__ float2 g_q [MTOK*DINNER];
__device__ float2 g_kv[MTOK*2*DINNER];
__device__ float  g_o4[4*BBATCH*NHEADS*NSEQ*DHD];
__device__ float2 g_oc[MTOK*DINNER];
__device__ float2 g_h1[MTOK*FFD];
__device__ float  g_cos[NSEQ*DHD];
__device__ float  g_sin[NSEQ*DHD];

// ---------------- small kernels ---------------------------------------------
__global__ void copy_in(const float2* __restrict__ x) {
    int i = blockIdx.x * 256 + threadIdx.x;
    g_x[i] = x[i];
}

__global__ void rope_table() {
    int i = blockIdx.x * 256 + threadIdx.x;
    if (i < NSEQ * DHD) {
        int n = i / DHD, d = i % DHD;
        float invf = powf(10000.0f, -((float)d) / (float)DHD);
        float f = (float)n * invf;
        g_cos[i] = cosf(f);
        g_sin[i] = sinf(f);
    }
}

__global__ void rmsnorm_k(const float2* __restrict__ in,
                          const float2* __restrict__ gamma,
                          float2* __restrict__ out) {
    int t = blockIdx.x;
    const float2* xp = in + (size_t)t * DIMC;
    __shared__ float red[256];
    float s = 0.f;
    for (int i = threadIdx.x; i < DIMC; i += 256) {
        float2 v = xp[i];
        s += v.x * v.x + v.y * v.y;
    }
    red[threadIdx.x] = s;
    __syncthreads();
    for (int o = 128; o > 0; o >>= 1) {
        if (threadIdx.x < o) red[threadIdx.x] += red[threadIdx.x + o];
        __syncthreads();
    }
    float inv = rsqrtf(red[0] / (float)DIMC + EPSV);
    for (int i = threadIdx.x; i < DIMC; i += 256) {
        float2 v = xp[i];
        float2 g = gamma[i];
        float xr = v.x * inv, xi = v.y * inv;
        out[(size_t)t * DIMC + i] = make_float2(xr * g.x - xi * g.y,
                                                xr * g.y + xi * g.x);
    }
}

// ---------------- tf32 mma helpers ------------------------------------------
__device__ __forceinline__ uint32_t f2tf(float x) {
    uint32_t r;
    asm("cvt.rna.tf32.f32 %0, %1;" : "=r"(r) : "f"(x));
    return r;
}

__device__ __forceinline__ void mma8(float* c, const uint32_t* a, const uint32_t* b) {
    asm volatile(
        "mma.sync.aligned.m16n8k8.row.col.f32.tf32.tf32.f32 "
        "{%0,%1,%2,%3}, {%4,%5,%6,%7}, {%8,%9}, {%0,%1,%2,%3};"
        : "+f"(c[0]), "+f"(c[1]), "+f"(c[2]), "+f"(c[3])
        : "r"(a[0]), "r"(a[1]), "r"(a[2]), "r"(a[3]), "r"(b[0]), "r"(b[1]));
}

// ---------------- tf32 tensor-core complex GEMM -----------------------------
#define BM 128
#define BN 64
#define BK 16

__global__ __launch_bounds__(256)
void cgemm_tc(const float2* __restrict__ A, const float2* __restrict__ W,
              const float2* __restrict__ bias, const float2* __restrict__ res,
              float2* __restrict__ C, int K, int N) {
    __shared__ float Asr[BM][20];
    __shared__ float Asi[BM][20];
    __shared__ float Bsr[BN][17];
    __shared__ float Bsi[BN][17];

    const int tid  = threadIdx.x;
    const int lane = tid & 31;
    const int warp = tid >> 5;
    const int mbase = (warp >> 1) * 32;
    const int nbase = (warp & 1) * 32;
    const int gr = lane >> 2;
    const int cc = lane & 3;
    const int m0 = blockIdx.y * BM;
    const int n0 = blockIdx.x * BN;

    float accr[2][4][4], acci[2][4][4];
#pragma unroll
    for (int mt = 0; mt < 2; mt++)
#pragma unroll
        for (int nt = 0; nt < 4; nt++)
#pragma unroll
            for (int e = 0; e < 4; e++) { accr[mt][nt][e] = 0.f; acci[mt][nt][e] = 0.f; }

    const int nkb = K / BK;
    float2 aReg[8], bReg[4];

#pragma unroll
    for (int t = 0; t < 8; t++) {
        int idx = tid + t * 256;
        int m = idx >> 4, kk = idx & 15;
        aReg[t] = A[(size_t)(m0 + m) * K + kk];
    }
#pragma unroll
    for (int t = 0; t < 4; t++) {
        int idx = tid + t * 256;
        int n = idx & 63, kk = idx >> 6;
        bReg[t] = W[(size_t)kk * N + n0 + n];
    }
#pragma unroll
    for (int t = 0; t < 8; t++) {
        int idx = tid + t * 256;
        int m = idx >> 4, kk = idx & 15;
        Asr[m][kk] = aReg[t].x; Asi[m][kk] = aReg[t].y;
    }
#pragma unroll
    for (int t = 0; t < 4; t++) {
        int idx = tid + t * 256;
        int n = idx & 63, kk = idx >> 6;
        Bsr[n][kk] = bReg[t].x; Bsi[n][kk] = bReg[t].y;
    }
    __syncthreads();

    for (int kb = 0; kb < nkb; kb++) {
        if (kb + 1 < nkb) {
            int k0 = (kb + 1) * BK;
#pragma unroll
            for (int t = 0; t < 8; t++) {
                int idx = tid + t * 256;
                int m = idx >> 4, kk = idx & 15;
                aReg[t] = A[(size_t)(m0 + m) * K + k0 + kk];
            }
#pragma unroll
            for (int t = 0; t < 4; t++) {
                int idx = tid + t * 256;
                int n = idx & 63, kk = idx >> 6;
                bReg[t] = W[(size_t)(k0 + kk) * N + n0 + n];
            }
        }

#pragma unroll
        for (int ks = 0; ks < BK; ks += 8) {
            uint32_t ar[2][4], ai[2][4], nai[2][4];
#pragma unroll
            for (int mt = 0; mt < 2; mt++) {
                int r = mbase + mt * 16 + gr;
                ar[mt][0] = f2tf(Asr[r][ks + cc]);
                ar[mt][1] = f2tf(Asr[r + 8][ks + cc]);
                ar[mt][2] = f2tf(Asr[r][ks + cc + 4]);
                ar[mt][3] = f2tf(Asr[r + 8][ks + cc + 4]);
                ai[mt][0] = f2tf(Asi[r][ks + cc]);
                ai[mt][1] = f2tf(Asi[r + 8][ks + cc]);
                ai[mt][2] = f2tf(Asi[r][ks + cc + 4]);
                ai[mt][3] = f2tf(Asi[r + 8][ks + cc + 4]);
#pragma unroll
                for (int e = 0; e < 4; e++) nai[mt][e] = ai[mt][e] ^ 0x80000000u;
            }
            uint32_t br[4][2], bi[4][2];
#pragma unroll
            for (int nt = 0; nt < 4; nt++) {
                int n = nbase + nt * 8 + gr;
                br[nt][0] = f2tf(Bsr[n][ks + cc]);
                br[nt][1] = f2tf(Bsr[n][ks + cc + 4]);
                bi[nt][0] = f2tf(Bsi[n][ks + cc]);
                bi[nt][1] = f2tf(Bsi[n][ks + cc + 4]);
            }
#pragma unroll
            for (int mt = 0; mt < 2; mt++)
#pragma unroll
                for (int nt = 0; nt < 4; nt++) {
                    mma8(accr[mt][nt], ar[mt],  br[nt]);
                    mma8(accr[mt][nt], nai[mt], bi[nt]);
                    mma8(acci[mt][nt], ar[mt],  bi[nt]);
                    mma8(acci[mt][nt], ai[mt],  br[nt]);
                }
        }
        __syncthreads();

        if (kb + 1 < nkb) {
#pragma unroll
            for (int t = 0; t < 8; t++) {
                int idx = tid + t * 256;
                int m = idx >> 4, kk = idx & 15;
                Asr[m][kk] = aReg[t].x; Asi[m][kk] = aReg[t].y;
            }
#pragma unroll
            for (int t = 0; t < 4; t++) {
                int idx = tid + t * 256;
                int n = idx & 63, kk = idx >> 6;
                Bsr[n][kk] = bReg[t].x; Bsi[n][kk] = bReg[t].y;
            }
            __syncthreads();
        }
    }

#pragma unroll
    for (int mt = 0; mt < 2; mt++)
#pragma unroll
        for (int nt = 0; nt < 4; nt++) {
#pragma unroll
            for (int half = 0; half < 2; half++) {
                int row = m0 + mbase + mt * 16 + gr + half * 8;
                int col = n0 + nbase + nt * 8 + cc * 2;
                float r0 = accr[mt][nt][half * 2 + 0];
                float i0 = acci[mt][nt][half * 2 + 0];
                float r1 = accr[mt][nt][half * 2 + 1];
                float i1 = acci[mt][nt][half * 2 + 1];
                if (bias) {
                    float2 b0 = bias[col], b1 = bias[col + 1];
                    r0 += b0.x; i0 += b0.y; r1 += b1.x; i1 += b1.y;
                }
                if (res) {
                    const float4 rr = *reinterpret_cast<const float4*>(res + (size_t)row * N + col);
                    r0 += rr.x; i0 += rr.y; r1 += rr.z; i1 += rr.w;
                }
                *reinterpret_cast<float4*>(C + (size_t)row * N + col) =
                    make_float4(r0, i0, r1, i1);
            }
        }
}

// ---------------- RoPE ------------------------------------------------------
__global__ void rope_apply(float2* __restrict__ buf, int rowStride) {
    int i = blockIdx.x * 256 + threadIdx.x;
    int e = i % DINNER;
    int n = (i / DINNER) % NSEQ;
    int b = i / (DINNER * NSEQ);
    int d = e % DHD;
    float c = g_cos[n * DHD + d], s = g_sin[n * DHD + d];
    float2* p = buf + (size_t)(b * NSEQ + n) * rowStride + e;
    float2 v = *p;
    *p = make_float2(v.x * c - v.y * s, v.x * s + v.y * c);
}

// ---------------- tensor-core flash attention -------------------------------
// grid (NSEQ/64, NHEADS, BBATCH*2). blockIdx.z = b*2 + qpart.
// Warps 0-3: replica S = q·kr. Warps 4-7: replica S = q·(-ki).
// Both replicas share Q, K, V smem tiles. V part = qpart (vr or vi).
// Output replica id r = half + 2*qpart  (matches [qr·kr, qr·-ki, qi·kr, qi·-ki]).
#define ASTR 68
#define VSTR 65
#define FA_SMEM ((5*64*ASTR + 64*VSTR)*4)

__global__ __launch_bounds__(256)
void flash_attn_tc() {
    extern __shared__ float sm[];
    float* Qs  = sm;                 // [64][ASTR]
    float* Ksr = Qs  + 64*ASTR;      // [64][ASTR]
    float* Ksi = Ksr + 64*ASTR;      // [64][ASTR]  (stores -ki)
    float* Pa  = Ksi + 64*ASTR;      // [64][ASTR]
    float* Pb  = Pa  + 64*ASTR;      // [64][ASTR]
    float* Vst = Pb  + 64*ASTR;      // [64][VSTR] transposed: [d][key]

    const int tid  = threadIdx.x;
    const int lane = tid & 31;
    const int warp = tid >> 5;
    const int half = warp >> 2;          // 0: q·kr, 1: q·(-ki)
    const int rbase = (warp & 3) * 16;
    const int gr = lane >> 2;
    const int cc = lane & 3;
    const int b = blockIdx.z >> 1;
    const int qpart = blockIdx.z & 1;
    const int h = blockIdx.y;
    const int q0 = blockIdx.x * 64;

    // load Q tile (select part, pre-scale)
    for (int i = tid; i < 64 * 64; i += 256) {
        int r = i >> 6, d = i & 63;
        float2 v = g_q[(size_t)(b * NSEQ + q0 + r) * DINNER + h * DHD + d];
        Qs[r * ASTR + d] = (qpart ? v.y : v.x) * SCALEV;
    }

    float m0 = -INFINITY, m1 = -INFINITY, l0 = 0.f, l1 = 0.f;
    float oacc[8][4];
#pragma unroll
    for (int nt = 0; nt < 8; nt++)
#pragma unroll
        for (int e = 0; e < 4; e++) oacc[nt][e] = 0.f;

    float* Ph = half ? Pb : Pa;

    for (int c0 = 0; c0 < NSEQ; c0 += 64) {
        __syncthreads();
        for (int i = tid; i < 64 * 64; i += 256) {
            int key = i >> 6, d = i & 63;
            const float2* p = g_kv + (size_t)(b * NSEQ + c0 + key) * (2 * DINNER) + h * DHD + d;
            float2 kc = p[0];
            float2 vc = p[DINNER];
            Ksr[key * ASTR + d] = kc.x;
            Ksi[key * ASTR + d] = -kc.y;
            Vst[d * VSTR + key] = qpart ? vc.y : vc.x;
        }
        __syncthreads();

        const float* Kp = half ? Ksi : Ksr;

        // S = Q · K^T  (16 rows x 64 keys per warp)
        float sacc[8][4];
#pragma unroll
        for (int nt = 0; nt < 8; nt++)
#pragma unroll
            for (int e = 0; e < 4; e++) sacc[nt][e] = 0.f;

#pragma unroll
        for (int kk = 0; kk < 64; kk += 8) {
            uint32_t a[4];
            a[0] = f2tf(Qs[(rbase + gr)     * ASTR + kk + cc]);
            a[1] = f2tf(Qs[(rbase + gr + 8) * ASTR + kk + cc]);
            a[2] = f2tf(Qs[(rbase + gr)     * ASTR + kk + cc + 4]);
            a[3] = f2tf(Qs[(rbase + gr + 8) * ASTR + kk + cc + 4]);
#pragma unroll
            for (int nt = 0; nt < 8; nt++) {
                uint32_t bb[2];
                bb[0] = f2tf(Kp[(nt * 8 + gr) * ASTR + kk + cc]);
                bb[1] = f2tf(Kp[(nt * 8 + gr) * ASTR + kk + cc + 4]);
                mma8(sacc[nt], a, bb);
            }
        }

        // online softmax (rows gr and gr+8; 4 lanes per row share via quad shfl)
        float rmax0 = -INFINITY, rmax1 = -INFINITY;
#pragma unroll
        for (int nt = 0; nt < 8; nt++) {
            rmax0 = fmaxf(rmax0, fmaxf(sacc[nt][0], sacc[nt][1]));
            rmax1 = fmaxf(rmax1, fmaxf(sacc[nt][2], sacc[nt][3]));
        }
        rmax0 = fmaxf(rmax0, __shfl_xor_sync(0xffffffffu, rmax0, 1));
        rmax0 = fmaxf(rmax0, __shfl_xor_sync(0xffffffffu, rmax0, 2));
        rmax1 = fmaxf(rmax1, __shfl_xor_sync(0xffffffffu, rmax1, 1));
        rmax1 = fmaxf(rmax1, __shfl_xor_sync(0xffffffffu, rmax1, 2));

        float mn0 = fmaxf(m0, rmax0);
        float mn1 = fmaxf(m1, rmax1);
        float corr0 = expf(m0 - mn0);
        float corr1 = expf(m1 - mn1);

        float ps0 = 0.f, ps1 = 0.f;
#pragma unroll
        for (int nt = 0; nt < 8; nt++) {
            float p00 = expf(sacc[nt][0] - mn0);
            float p01 = expf(sacc[nt][1] - mn0);
            float p10 = expf(sacc[nt][2] - mn1);
            float p11 = expf(sacc[nt][3] - mn1);
            ps0 += p00 + p01;
            ps1 += p10 + p11;
            *reinterpret_cast<float2*>(&Ph[(rbase + gr)     * ASTR + nt * 8 + 2 * cc]) = make_float2(p00, p01);
            *reinterpret_cast<float2*>(&Ph[(rbase + gr + 8) * ASTR + nt * 8 + 2 * cc]) = make_float2(p10, p11);
        }
        ps0 += __shfl_xor_sync(0xffffffffu, ps0, 1);
        ps0 += __shfl_xor_sync(0xffffffffu, ps0, 2);
        ps1 += __shfl_xor_sync(0xffffffffu, ps1, 1);
        ps1 += __shfl_xor_sync(0xffffffffu, ps1, 2);

        l0 = l0 * corr0 + ps0;
        l1 = l1 * corr1 + ps1;
#pragma unroll
        for (int nt = 0; nt < 8; nt++) {
            oacc[nt][0] *= corr0; oacc[nt][1] *= corr0;
            oacc[nt][2] *= corr1; oacc[nt][3] *= corr1;
        }
        m0 = mn0; m1 = mn1;

        // O += P · V  (same warp wrote its own P rows -> no barrier needed)
#pragma unroll
        for (int kk = 0; kk < 64; kk += 8) {
            uint32_t a[4];
            a[0] = f2tf(Ph[(rbase + gr)     * ASTR + kk + cc]);
            a[1] = f2tf(Ph[(rbase + gr + 8) * ASTR + kk + cc]);
            a[2] = f2tf(Ph[(rbase + gr)     * ASTR + kk + cc + 4]);
            a[3] = f2tf(Ph[(rbase + gr + 8) * ASTR + kk + cc + 4]);
#pragma unroll
            for (int nt = 0; nt < 8; nt++) {
                uint32_t bb[2];
                bb[0] = f2tf(Vst[(nt * 8 + gr) * VSTR + kk + cc]);
                bb[1] = f2tf(Vst[(nt * 8 + gr) * VSTR + kk + cc + 4]);
                mma8(oacc[nt], a, bb);
            }
        }
    }

    // epilogue
    float inv0 = 1.f / l0;
    float inv1 = 1.f / l1;
    int r = half + qpart * 2;
    size_t rowb = ((size_t)((r * BBATCH + b) * NHEADS + h) * NSEQ + q0 + rbase);
#pragma unroll
    for (int nt = 0; nt < 8; nt++) {
        int col = nt * 8 + 2 * cc;
        *reinterpret_cast<float2*>(&g_o4[(rowb + gr) * DHD + col]) =
            make_float2(oacc[nt][0] * inv0, oacc[nt][1] * inv0);
        *reinterpret_cast<float2*>(&g_o4[(rowb + gr + 8) * DHD + col]) =
            make_float2(oacc[nt][2] * inv1, oacc[nt][3] * inv1);
    }
}

__global__ void combine_o() {
    int i = blockIdx.x * 256 + threadIdx.x;
    int d  = i % DHD;
    int hh = (i / DHD) % NHEADS;
    int n  = (i / DINNER) % NSEQ;
    int b  = i / (DINNER * NSEQ);
    size_t idx4 = ((size_t)(b * NHEADS + hh) * NSEQ + n) * DHD + d;
    const size_t plane = (size_t)BBATCH * NHEADS * NSEQ * DHD;
    float rr = g_o4[idx4];
    float ri = g_o4[plane + idx4];
    float ir = g_o4[2 * plane + idx4];
    float ii = g_o4[3 * plane + idx4];
    g_oc[i] = make_float2(rr - ii, ri + ir);
}

__global__ void nonlin_k(const float* __restrict__ mod_bias, int layer) {
    int i = blockIdx.x * 256 + threadIdx.x;
    float2 v = g_h1[i];
    float mag = sqrtf(v.x * v.x + v.y * v.y);
    float t = mag + mod_bias[layer];
    float c = t > 0.f ? t * t : 0.f;
    float2 out;
    if (mag > 0.f) {
        float sc = c / mag;
        out = make_float2(v.x * sc, v.y * sc);
    } else {
        out = make_float2(c, 0.f);
    }
    g_h1[i] = out;
}

// ---------------- host orchestration ---------------------------------------
extern "C" void kernel_launch(void* const* d_in, const int* in_sizes, int n_in,
                              void* d_out, int out_size) {
    const float2* x           = (const float2*)d_in[0];
    const float2* gamma_attn  = (const float2*)d_in[1];
    const float2* Wq          = (const float2*)d_in[2];
    const float2* Wkv         = (const float2*)d_in[3];
    const float2* Wo          = (const float2*)d_in[4];
    const float2* gamma_ff    = (const float2*)d_in[5];
    const float2* W1          = (const float2*)d_in[6];
    const float2* b1          = (const float2*)d_in[7];
    const float*  mod_bias    = (const float*)d_in[8];
    const float2* W2          = (const float2*)d_in[9];
    const float2* b2          = (const float2*)d_in[10];
    const float2* gamma_final = (const float2*)d_in[11];

    float2 *px, *ph, *pq, *pkv, *poc, *ph1;
    cudaGetSymbolAddress((void**)&px,  g_x);
    cudaGetSymbolAddress((void**)&ph,  g_h);
    cudaGetSymbolAddress((void**)&pq,  g_q);
    cudaGetSymbolAddress((void**)&pkv, g_kv);
    cudaGetSymbolAddress((void**)&poc, g_oc);
    cudaGetSymbolAddress((void**)&ph1, g_h1);

    cudaFuncSetAttribute(flash_attn_tc,
                         cudaFuncAttributeMaxDynamicSharedMemorySize, FA_SMEM);

    copy_in<<<MTOK * DIMC / 256, 256>>>(x);
    rope_table<<<(NSEQ * DHD + 255) / 256, 256>>>();

    for (int l = 0; l < NDEPTH; l++) {
        rmsnorm_k<<<MTOK, 256>>>(px, gamma_attn + (size_t)l * DIMC, ph);
        cgemm_tc<<<dim3(DINNER / BN, MTOK / BM), 256>>>(
            ph, Wq + (size_t)l * DIMC * DINNER, nullptr, nullptr, pq, DIMC, DINNER);
        cgemm_tc<<<dim3(2 * DINNER / BN, MTOK / BM), 256>>>(
            ph, Wkv + (size_t)l * DIMC * 2 * DINNER, nullptr, nullptr, pkv, DIMC, 2 * DINNER);
        rope_apply<<<BBATCH * NSEQ * DINNER / 256, 256>>>(pq, DINNER);
        rope_apply<<<BBATCH * NSEQ * DINNER / 256, 256>>>(pkv, 2 * DINNER);
        flash_attn_tc<<<dim3(NSEQ / 64, NHEADS, BBATCH * 2), 256, FA_SMEM>>>();
        combine_o<<<BBATCH * NSEQ * DINNER / 256, 256>>>();
        cgemm_tc<<<dim3(DIMC / BN, MTOK / BM), 256>>>(
            poc, Wo + (size_t)l * DINNER * DIMC, nullptr, px, px, DINNER, DIMC);

        rmsnorm_k<<<MTOK, 256>>>(px, gamma_ff + (size_t)l * DIMC, ph);
        cgemm_tc<<<dim3(FFD / BN, MTOK / BM), 256>>>(
            ph, W1 + (size_t)l * DIMC * FFD, b1 + (size_t)l * FFD, nullptr, ph1, DIMC, FFD);
        nonlin_k<<<MTOK * FFD / 256, 256>>>(mod_bias, l);
        cgemm_tc<<<dim3(DIMC / BN, MTOK / BM), 256>>>(
            ph1, W2 + (size_t)l * FFD * DIMC, b2 + (size_t)l * DIMC, px, px, FFD, DIMC);
    }

    rmsnorm_k<<<MTOK, 256>>>(px, gamma_final, (float2*)d_out);
}

// round 5
// speedup vs baseline: 4.4157x; 1.0199x over previous
#include <cuda_runtime.h>
#include <math.h>
#include <stdint.h>

#define DIMC   512
#define NHEADS 8
#define DHD    64
#define NDEPTH 2
#define BBATCH 2
#define NSEQ   1024
#define DINNER 512
#define FFD    2048
#define MTOK   (BBATCH*NSEQ)
#define EPSV   1e-6f
#define SCALEV 0.125f

// epilogue modes for cgemm
#define EP_NONE   0
#define EP_ROPE   1   // rope on all columns (q projection)
#define EP_ROPE_K 2   // rope on cols < DINNER only (kv projection)
#define EP_NONLIN 3   // magnitude nonlinearity (W1 output)

// ---------------- scratch ---------------------------------------------------
__device__ float2 g_x [MTOK*DIMC];
__device__ float2 g_h [MTOK*DIMC];
__device__ float2 g_q [MTOK*DINNER];
__device__ float2 g_kv[MTOK*2*DINNER];
__device__ float  g_o4[4*BBATCH*NHEADS*NSEQ*DHD];
__device__ float2 g_oc[MTOK*DINNER];
__device__ float2 g_h1[MTOK*FFD];
__device__ float  g_cos[NSEQ*DHD];
__device__ float  g_sin[NSEQ*DHD];

// ---------------- small kernels ---------------------------------------------
__global__ void rope_table() {
    int i = blockIdx.x * 256 + threadIdx.x;
    if (i < NSEQ * DHD) {
        int n = i / DHD, d = i % DHD;
        float invf = powf(10000.0f, -((float)d) / (float)DHD);
        float f = (float)n * invf;
        g_cos[i] = cosf(f);
        g_sin[i] = sinf(f);
    }
}

__global__ void rmsnorm_k(const float2* __restrict__ in,
                          const float2* __restrict__ gamma,
                          float2* __restrict__ out) {
    int t = blockIdx.x;
    const float2* xp = in + (size_t)t * DIMC;
    __shared__ float red[256];
    float s = 0.f;
    for (int i = threadIdx.x; i < DIMC; i += 256) {
        float2 v = xp[i];
        s += v.x * v.x + v.y * v.y;
    }
    red[threadIdx.x] = s;
    __syncthreads();
    for (int o = 128; o > 0; o >>= 1) {
        if (threadIdx.x < o) red[threadIdx.x] += red[threadIdx.x + o];
        __syncthreads();
    }
    float inv = rsqrtf(red[0] / (float)DIMC + EPSV);
    for (int i = threadIdx.x; i < DIMC; i += 256) {
        float2 v = xp[i];
        float2 g = gamma[i];
        float xr = v.x * inv, xi = v.y * inv;
        out[(size_t)t * DIMC + i] = make_float2(xr * g.x - xi * g.y,
                                                xr * g.y + xi * g.x);
    }
}

// ---------------- tf32 mma helpers ------------------------------------------
__device__ __forceinline__ uint32_t f2tf(float x) {
    uint32_t r;
    asm("cvt.rna.tf32.f32 %0, %1;" : "=r"(r) : "f"(x));
    return r;
}

__device__ __forceinline__ void mma8(float* c, const uint32_t* a, const uint32_t* b) {
    asm volatile(
        "mma.sync.aligned.m16n8k8.row.col.f32.tf32.tf32.f32 "
        "{%0,%1,%2,%3}, {%4,%5,%6,%7}, {%8,%9}, {%0,%1,%2,%3};"
        : "+f"(c[0]), "+f"(c[1]), "+f"(c[2]), "+f"(c[3])
        : "r"(a[0]), "r"(a[1]), "r"(a[2]), "r"(a[3]), "r"(b[0]), "r"(b[1]));
}

__device__ __forceinline__ void apply_nl(float& r, float& i, float mb) {
    float mag = sqrtf(r * r + i * i);
    float t = mag + mb;
    float c = t > 0.f ? t * t : 0.f;
    if (mag > 0.f) { float sc = c / mag; r *= sc; i *= sc; }
    else { r = c; i = 0.f; }
}

// ---------------- tf32 tensor-core complex GEMM -----------------------------
// smem holds tf32-converted bits; inner loop is LDS + HMMA only.
#define BM 128
#define BN 64
#define BK 16
#define GASTR 20
#define GBSTR 20

__global__ __launch_bounds__(256)
void cgemm_tc(const float2* __restrict__ A, const float2* __restrict__ W,
              const float2* __restrict__ bias, const float2* __restrict__ res,
              float2* __restrict__ C, int K, int N,
              int mode, const float* __restrict__ mb) {
    __shared__ uint32_t Asr[BM][GASTR];
    __shared__ uint32_t Asi[BM][GASTR];
    __shared__ uint32_t Bsr[BN][GBSTR];
    __shared__ uint32_t Bsi[BN][GBSTR];

    const int tid  = threadIdx.x;
    const int lane = tid & 31;
    const int warp = tid >> 5;
    const int mbase = (warp >> 1) * 32;
    const int nbase = (warp & 1) * 32;
    const int gr = lane >> 2;
    const int cc = lane & 3;
    const int m0 = blockIdx.y * BM;
    const int n0 = blockIdx.x * BN;

    float accr[2][4][4], acci[2][4][4];
#pragma unroll
    for (int mt = 0; mt < 2; mt++)
#pragma unroll
        for (int nt = 0; nt < 4; nt++)
#pragma unroll
            for (int e = 0; e < 4; e++) { accr[mt][nt][e] = 0.f; acci[mt][nt][e] = 0.f; }

    const int nkb = K / BK;
    float2 aReg[8], bReg[4];

#pragma unroll
    for (int t = 0; t < 8; t++) {
        int idx = tid + t * 256;
        aReg[t] = A[(size_t)(m0 + (idx >> 4)) * K + (idx & 15)];
    }
#pragma unroll
    for (int t = 0; t < 4; t++) {
        int idx = tid + t * 256;
        bReg[t] = W[(size_t)(idx >> 6) * N + n0 + (idx & 63)];
    }
#pragma unroll
    for (int t = 0; t < 8; t++) {
        int idx = tid + t * 256;
        int m = idx >> 4, kk = idx & 15;
        Asr[m][kk] = f2tf(aReg[t].x); Asi[m][kk] = f2tf(aReg[t].y);
    }
#pragma unroll
    for (int t = 0; t < 4; t++) {
        int idx = tid + t * 256;
        int n = idx & 63, kk = idx >> 6;
        Bsr[n][kk] = f2tf(bReg[t].x); Bsi[n][kk] = f2tf(bReg[t].y);
    }
    __syncthreads();

    for (int kb = 0; kb < nkb; kb++) {
        if (kb + 1 < nkb) {
            int k0 = (kb + 1) * BK;
#pragma unroll
            for (int t = 0; t < 8; t++) {
                int idx = tid + t * 256;
                aReg[t] = A[(size_t)(m0 + (idx >> 4)) * K + k0 + (idx & 15)];
            }
#pragma unroll
            for (int t = 0; t < 4; t++) {
                int idx = tid + t * 256;
                bReg[t] = W[(size_t)(k0 + (idx >> 6)) * N + n0 + (idx & 63)];
            }
        }

#pragma unroll
        for (int ks = 0; ks < BK; ks += 8) {
            uint32_t ar[2][4], ai[2][4], nai[2][4];
#pragma unroll
            for (int mt = 0; mt < 2; mt++) {
                int r = mbase + mt * 16 + gr;
                ar[mt][0] = Asr[r][ks + cc];
                ar[mt][1] = Asr[r + 8][ks + cc];
                ar[mt][2] = Asr[r][ks + cc + 4];
                ar[mt][3] = Asr[r + 8][ks + cc + 4];
                ai[mt][0] = Asi[r][ks + cc];
                ai[mt][1] = Asi[r + 8][ks + cc];
                ai[mt][2] = Asi[r][ks + cc + 4];
                ai[mt][3] = Asi[r + 8][ks + cc + 4];
#pragma unroll
                for (int e = 0; e < 4; e++) nai[mt][e] = ai[mt][e] ^ 0x80000000u;
            }
            uint32_t br[4][2], bi[4][2];
#pragma unroll
            for (int nt = 0; nt < 4; nt++) {
                int n = nbase + nt * 8 + gr;
                br[nt][0] = Bsr[n][ks + cc];
                br[nt][1] = Bsr[n][ks + cc + 4];
                bi[nt][0] = Bsi[n][ks + cc];
                bi[nt][1] = Bsi[n][ks + cc + 4];
            }
#pragma unroll
            for (int mt = 0; mt < 2; mt++)
#pragma unroll
                for (int nt = 0; nt < 4; nt++) {
                    mma8(accr[mt][nt], ar[mt],  br[nt]);
                    mma8(accr[mt][nt], nai[mt], bi[nt]);
                    mma8(acci[mt][nt], ar[mt],  bi[nt]);
                    mma8(acci[mt][nt], ai[mt],  br[nt]);
                }
        }
        __syncthreads();

        if (kb + 1 < nkb) {
#pragma unroll
            for (int t = 0; t < 8; t++) {
                int idx = tid + t * 256;
                int m = idx >> 4, kk = idx & 15;
                Asr[m][kk] = f2tf(aReg[t].x); Asi[m][kk] = f2tf(aReg[t].y);
            }
#pragma unroll
            for (int t = 0; t < 4; t++) {
                int idx = tid + t * 256;
                int n = idx & 63, kk = idx >> 6;
                Bsr[n][kk] = f2tf(bReg[t].x); Bsi[n][kk] = f2tf(bReg[t].y);
            }
            __syncthreads();
        }
    }

#pragma unroll
    for (int mt = 0; mt < 2; mt++)
#pragma unroll
        for (int nt = 0; nt < 4; nt++) {
#pragma unroll
            for (int half = 0; half < 2; half++) {
                int row = m0 + mbase + mt * 16 + gr + half * 8;
                int col = n0 + nbase + nt * 8 + cc * 2;
                float r0 = accr[mt][nt][half * 2 + 0];
                float i0 = acci[mt][nt][half * 2 + 0];
                float r1 = accr[mt][nt][half * 2 + 1];
                float i1 = acci[mt][nt][half * 2 + 1];
                if (bias) {
                    float2 b0 = bias[col], b1 = bias[col + 1];
                    r0 += b0.x; i0 += b0.y; r1 += b1.x; i1 += b1.y;
                }
                if (mode == EP_ROPE || (mode == EP_ROPE_K && col < DINNER)) {
                    int n = row & (NSEQ - 1);
                    int d0 = col & 63, d1 = (col + 1) & 63;
                    float c0 = g_cos[n * DHD + d0], s0 = g_sin[n * DHD + d0];
                    float c1 = g_cos[n * DHD + d1], s1 = g_sin[n * DHD + d1];
                    float t0 = r0 * c0 - i0 * s0; i0 = r0 * s0 + i0 * c0; r0 = t0;
                    float t1 = r1 * c1 - i1 * s1; i1 = r1 * s1 + i1 * c1; r1 = t1;
                } else if (mode == EP_NONLIN) {
                    float mbv = *mb;
                    apply_nl(r0, i0, mbv);
                    apply_nl(r1, i1, mbv);
                }
                if (res) {
                    const float4 rr = *reinterpret_cast<const float4*>(res + (size_t)row * N + col);
                    r0 += rr.x; i0 += rr.y; r1 += rr.z; i1 += rr.w;
                }
                *reinterpret_cast<float4*>(C + (size_t)row * N + col) =
                    make_float4(r0, i0, r1, i1);
            }
        }
}

// ---------------- tensor-core flash attention -------------------------------
#define ASTR 68
#define VSTR 68
#define FA_SMEM ((5*64*ASTR + 64*VSTR)*4)

__global__ __launch_bounds__(256)
void flash_attn_tc() {
    extern __shared__ uint32_t sm[];
    uint32_t* Qs  = sm;
    uint32_t* Ksr = Qs  + 64*ASTR;
    uint32_t* Ksi = Ksr + 64*ASTR;   // holds -ki (tf32)
    uint32_t* Pa  = Ksi + 64*ASTR;
    uint32_t* Pb  = Pa  + 64*ASTR;
    uint32_t* Vst = Pb  + 64*ASTR;   // transposed [d][key]

    const int tid  = threadIdx.x;
    const int lane = tid & 31;
    const int warp = tid >> 5;
    const int half = warp >> 2;
    const int rbase = (warp & 3) * 16;
    const int gr = lane >> 2;
    const int cc = lane & 3;
    const int b = blockIdx.z >> 1;
    const int qpart = blockIdx.z & 1;
    const int h = blockIdx.y;
    const int q0 = blockIdx.x * 64;

    for (int i = tid; i < 64 * 64; i += 256) {
        int r = i >> 6, d = i & 63;
        float2 v = g_q[(size_t)(b * NSEQ + q0 + r) * DINNER + h * DHD + d];
        Qs[r * ASTR + d] = f2tf((qpart ? v.y : v.x) * SCALEV);
    }

    float m0 = -INFINITY, m1 = -INFINITY, l0 = 0.f, l1 = 0.f;
    float oacc[8][4];
#pragma unroll
    for (int nt = 0; nt < 8; nt++)
#pragma unroll
        for (int e = 0; e < 4; e++) oacc[nt][e] = 0.f;

    uint32_t* Ph = half ? Pb : Pa;

    for (int c0 = 0; c0 < NSEQ; c0 += 64) {
        __syncthreads();
        for (int i = tid; i < 64 * 64; i += 256) {
            int key = i >> 6, d = i & 63;
            const float2* p = g_kv + (size_t)(b * NSEQ + c0 + key) * (2 * DINNER) + h * DHD + d;
            float2 kc = p[0];
            float2 vc = p[DINNER];
            Ksr[key * ASTR + d] = f2tf(kc.x);
            Ksi[key * ASTR + d] = f2tf(-kc.y);
            Vst[d * VSTR + key] = f2tf(qpart ? vc.y : vc.x);
        }
        __syncthreads();

        const uint32_t* Kp = half ? Ksi : Ksr;

        float sacc[8][4];
#pragma unroll
        for (int nt = 0; nt < 8; nt++)
#pragma unroll
            for (int e = 0; e < 4; e++) sacc[nt][e] = 0.f;

#pragma unroll
        for (int kk = 0; kk < 64; kk += 8) {
            uint32_t a[4];
            a[0] = Qs[(rbase + gr)     * ASTR + kk + cc];
            a[1] = Qs[(rbase + gr + 8) * ASTR + kk + cc];
            a[2] = Qs[(rbase + gr)     * ASTR + kk + cc + 4];
            a[3] = Qs[(rbase + gr + 8) * ASTR + kk + cc + 4];
#pragma unroll
            for (int nt = 0; nt < 8; nt++) {
                uint32_t bb[2];
                bb[0] = Kp[(nt * 8 + gr) * ASTR + kk + cc];
                bb[1] = Kp[(nt * 8 + gr) * ASTR + kk + cc + 4];
                mma8(sacc[nt], a, bb);
            }
        }

        float rmax0 = -INFINITY, rmax1 = -INFINITY;
#pragma unroll
        for (int nt = 0; nt < 8; nt++) {
            rmax0 = fmaxf(rmax0, fmaxf(sacc[nt][0], sacc[nt][1]));
            rmax1 = fmaxf(rmax1, fmaxf(sacc[nt][2], sacc[nt][3]));
        }
        rmax0 = fmaxf(rmax0, __shfl_xor_sync(0xffffffffu, rmax0, 1));
        rmax0 = fmaxf(rmax0, __shfl_xor_sync(0xffffffffu, rmax0, 2));
        rmax1 = fmaxf(rmax1, __shfl_xor_sync(0xffffffffu, rmax1, 1));
        rmax1 = fmaxf(rmax1, __shfl_xor_sync(0xffffffffu, rmax1, 2));

        float mn0 = fmaxf(m0, rmax0);
        float mn1 = fmaxf(m1, rmax1);
        float corr0 = expf(m0 - mn0);
        float corr1 = expf(m1 - mn1);

        float ps0 = 0.f, ps1 = 0.f;
#pragma unroll
        for (int nt = 0; nt < 8; nt++) {
            float p00 = expf(sacc[nt][0] - mn0);
            float p01 = expf(sacc[nt][1] - mn0);
            float p10 = expf(sacc[nt][2] - mn1);
            float p11 = expf(sacc[nt][3] - mn1);
            ps0 += p00 + p01;
            ps1 += p10 + p11;
            uint2 u0 = make_uint2(f2tf(p00), f2tf(p01));
            uint2 u1 = make_uint2(f2tf(p10), f2tf(p11));
            *reinterpret_cast<uint2*>(&Ph[(rbase + gr)     * ASTR + nt * 8 + 2 * cc]) = u0;
            *reinterpret_cast<uint2*>(&Ph[(rbase + gr + 8) * ASTR + nt * 8 + 2 * cc]) = u1;
        }
        ps0 += __shfl_xor_sync(0xffffffffu, ps0, 1);
        ps0 += __shfl_xor_sync(0xffffffffu, ps0, 2);
        ps1 += __shfl_xor_sync(0xffffffffu, ps1, 1);
        ps1 += __shfl_xor_sync(0xffffffffu, ps1, 2);

        l0 = l0 * corr0 + ps0;
        l1 = l1 * corr1 + ps1;
#pragma unroll
        for (int nt = 0; nt < 8; nt++) {
            oacc[nt][0] *= corr0; oacc[nt][1] *= corr0;
            oacc[nt][2] *= corr1; oacc[nt][3] *= corr1;
        }
        m0 = mn0; m1 = mn1;

#pragma unroll
        for (int kk = 0; kk < 64; kk += 8) {
            uint32_t a[4];
            a[0] = Ph[(rbase + gr)     * ASTR + kk + cc];
            a[1] = Ph[(rbase + gr + 8) * ASTR + kk + cc];
            a[2] = Ph[(rbase + gr)     * ASTR + kk + cc + 4];
            a[3] = Ph[(rbase + gr + 8) * ASTR + kk + cc + 4];
#pragma unroll
            for (int nt = 0; nt < 8; nt++) {
                uint32_t bb[2];
                bb[0] = Vst[(nt * 8 + gr) * VSTR + kk + cc];
                bb[1] = Vst[(nt * 8 + gr) * VSTR + kk + cc + 4];
                mma8(oacc[nt], a, bb);
            }
        }
    }

    float inv0 = 1.f / l0;
    float inv1 = 1.f / l1;
    int r = half + qpart * 2;
    size_t rowb = ((size_t)((r * BBATCH + b) * NHEADS + h) * NSEQ + q0 + rbase);
#pragma unroll
    for (int nt = 0; nt < 8; nt++) {
        int col = nt * 8 + 2 * cc;
        *reinterpret_cast<float2*>(&g_o4[(rowb + gr) * DHD + col]) =
            make_float2(oacc[nt][0] * inv0, oacc[nt][1] * inv0);
        *reinterpret_cast<float2*>(&g_o4[(rowb + gr + 8) * DHD + col]) =
            make_float2(oacc[nt][2] * inv1, oacc[nt][3] * inv1);
    }
}

__global__ void combine_o() {
    int i = blockIdx.x * 256 + threadIdx.x;
    int d  = i % DHD;
    int hh = (i / DHD) % NHEADS;
    int n  = (i / DINNER) % NSEQ;
    int b  = i / (DINNER * NSEQ);
    size_t idx4 = ((size_t)(b * NHEADS + hh) * NSEQ + n) * DHD + d;
    const size_t plane = (size_t)BBATCH * NHEADS * NSEQ * DHD;
    float rr = g_o4[idx4];
    float ri = g_o4[plane + idx4];
    float ir = g_o4[2 * plane + idx4];
    float ii = g_o4[3 * plane + idx4];
    g_oc[i] = make_float2(rr - ii, ri + ir);
}

// ---------------- host orchestration ---------------------------------------
extern "C" void kernel_launch(void* const* d_in, const int* in_sizes, int n_in,
                              void* d_out, int out_size) {
    const float2* x           = (const float2*)d_in[0];
    const float2* gamma_attn  = (const float2*)d_in[1];
    const float2* Wq          = (const float2*)d_in[2];
    const float2* Wkv         = (const float2*)d_in[3];
    const float2* Wo          = (const float2*)d_in[4];
    const float2* gamma_ff    = (const float2*)d_in[5];
    const float2* W1          = (const float2*)d_in[6];
    const float2* b1          = (const float2*)d_in[7];
    const float*  mod_bias    = (const float*)d_in[8];
    const float2* W2          = (const float2*)d_in[9];
    const float2* b2          = (const float2*)d_in[10];
    const float2* gamma_final = (const float2*)d_in[11];

    float2 *px, *ph, *pq, *pkv, *poc, *ph1;
    cudaGetSymbolAddress((void**)&px,  g_x);
    cudaGetSymbolAddress((void**)&ph,  g_h);
    cudaGetSymbolAddress((void**)&pq,  g_q);
    cudaGetSymbolAddress((void**)&pkv, g_kv);
    cudaGetSymbolAddress((void**)&poc, g_oc);
    cudaGetSymbolAddress((void**)&ph1, g_h1);

    cudaFuncSetAttribute(flash_attn_tc,
                         cudaFuncAttributeMaxDynamicSharedMemorySize, FA_SMEM);

    rope_table<<<(NSEQ * DHD + 255) / 256, 256>>>();

    for (int l = 0; l < NDEPTH; l++) {
        const float2* r0 = (l == 0) ? x : px;   // residual stream source

        rmsnorm_k<<<MTOK, 256>>>(r0, gamma_attn + (size_t)l * DIMC, ph);
        cgemm_tc<<<dim3(DINNER / BN, MTOK / BM), 256>>>(
            ph, Wq + (size_t)l * DIMC * DINNER, nullptr, nullptr, pq,
            DIMC, DINNER, EP_ROPE, nullptr);
        cgemm_tc<<<dim3(2 * DINNER / BN, MTOK / BM), 256>>>(
            ph, Wkv + (size_t)l * DIMC * 2 * DINNER, nullptr, nullptr, pkv,
            DIMC, 2 * DINNER, EP_ROPE_K, nullptr);
        flash_attn_tc<<<dim3(NSEQ / 64, NHEADS, BBATCH * 2), 256, FA_SMEM>>>();
        combine_o<<<BBATCH * NSEQ * DINNER / 256, 256>>>();
        cgemm_tc<<<dim3(DIMC / BN, MTOK / BM), 256>>>(
            poc, Wo + (size_t)l * DINNER * DIMC, nullptr, r0, px,
            DINNER, DIMC, EP_NONE, nullptr);

        rmsnorm_k<<<MTOK, 256>>>(px, gamma_ff + (size_t)l * DIMC, ph);
        cgemm_tc<<<dim3(FFD / BN, MTOK / BM), 256>>>(
            ph, W1 + (size_t)l * DIMC * FFD, b1 + (size_t)l * FFD, nullptr, ph1,
            DIMC, FFD, EP_NONLIN, mod_bias + l);
        cgemm_tc<<<dim3(DIMC / BN, MTOK / BM), 256>>>(
            ph1, W2 + (size_t)l * FFD * DIMC, b2 + (size_t)l * DIMC, px, px,
            FFD, DIMC, EP_NONE, nullptr);
    }

    rmsnorm_k<<<MTOK, 256>>>(px, gamma_final, (float2*)d_out);
}